// round 1
// baseline (speedup 1.0000x reference)
#include <cuda_runtime.h>
#include <math.h>

#define B_ 512
#define C_ 3
#define N_ 1024
#define D_ 2048
#define CD (C_*D_)
#define CN (C_*N_)
#define TAU 0.1f
#define LAM 0.1f
#define NLAYERS 30

// Scratch (static device globals; no allocation in kernel_launch)
__device__ float g_gram[(size_t)C_ * D_ * D_];   // 48 MB: per-channel Gram W W^T
__device__ float g_y[(size_t)B_ * C_ * D_];      // x W^T
__device__ float g_b0[(size_t)B_ * C_ * D_];
__device__ float g_b1[(size_t)B_ * C_ * D_];
__device__ float g_b2[(size_t)B_ * C_ * D_];
__device__ float g_b3[(size_t)B_ * C_ * D_];

__global__ void zero2_kernel(float* __restrict__ a, float* __restrict__ b, int n) {
    int i = blockIdx.x * blockDim.x + threadIdx.x;
    if (i < n) { a[i] = 0.f; b[i] = 0.f; }
}

// ---------------------------------------------------------------------------
// Generic batched NT GEMM: C[z][i,j] = sum_k A[z][i*lda+k] * B[z][j*ldb+k]
// Tiles: 128x128x16, 256 threads, 8x8 per-thread microtile.
// All problem dims here are exact multiples of the tile — no bounds checks.
// ---------------------------------------------------------------------------
__global__ __launch_bounds__(256, 2) void gemm_nt_k(
    const float* __restrict__ A, int lda, size_t sA,
    const float* __restrict__ Bp, int ldb, size_t sB,
    float* __restrict__ Cp, int ldc, size_t sC, int K)
{
    const int BM = 128, BN = 128, BK = 16;
    __shared__ float As[BK][BM];
    __shared__ float Bs[BK][BN];

    A  += (size_t)blockIdx.z * sA;
    Bp += (size_t)blockIdx.z * sB;
    Cp += (size_t)blockIdx.z * sC;

    const int row0 = blockIdx.y * BM;
    const int col0 = blockIdx.x * BN;
    const int tid = threadIdx.x;
    const int tx = tid & 15;     // 16 cols of threads
    const int ty = tid >> 4;     // 16 rows of threads

    float acc[8][8];
#pragma unroll
    for (int i = 0; i < 8; i++)
#pragma unroll
        for (int j = 0; j < 8; j++) acc[i][j] = 0.f;

    for (int kt = 0; kt < K; kt += BK) {
#pragma unroll
        for (int l = 0; l < 2; l++) {
            int v = tid + l * 256;
            int m = v >> 2;
            int kq = (v & 3) << 2;
            float4 f = *(const float4*)(A + (size_t)(row0 + m) * lda + kt + kq);
            As[kq + 0][m] = f.x; As[kq + 1][m] = f.y;
            As[kq + 2][m] = f.z; As[kq + 3][m] = f.w;
        }
#pragma unroll
        for (int l = 0; l < 2; l++) {
            int v = tid + l * 256;
            int n = v >> 2;
            int kq = (v & 3) << 2;
            float4 f = *(const float4*)(Bp + (size_t)(col0 + n) * ldb + kt + kq);
            Bs[kq + 0][n] = f.x; Bs[kq + 1][n] = f.y;
            Bs[kq + 2][n] = f.z; Bs[kq + 3][n] = f.w;
        }
        __syncthreads();

#pragma unroll
        for (int k = 0; k < BK; k++) {
            float a[8], b[8];
            *(float4*)&a[0] = *(const float4*)&As[k][ty * 8];
            *(float4*)&a[4] = *(const float4*)&As[k][ty * 8 + 4];
            *(float4*)&b[0] = *(const float4*)&Bs[k][tx * 8];
            *(float4*)&b[4] = *(const float4*)&Bs[k][tx * 8 + 4];
#pragma unroll
            for (int i = 0; i < 8; i++)
#pragma unroll
                for (int j = 0; j < 8; j++)
                    acc[i][j] = fmaf(a[i], b[j], acc[i][j]);
        }
        __syncthreads();
    }

#pragma unroll
    for (int i = 0; i < 8; i++) {
        size_t base = (size_t)(row0 + ty * 8 + i) * ldc + col0 + tx * 8;
        float4 o0 = make_float4(acc[i][0], acc[i][1], acc[i][2], acc[i][3]);
        float4 o1 = make_float4(acc[i][4], acc[i][5], acc[i][6], acc[i][7]);
        *(float4*)&Cp[base] = o0;
        *(float4*)&Cp[base + 4] = o1;
    }
}

// ---------------------------------------------------------------------------
// One fused FISTA iteration for one channel (blockIdx.z = c):
//   acc = x_tmp @ Gram_c          (Gram symmetric -> read rows, NT form)
//   v   = x_tmp - TAU*acc + TAU*y
//   group soft-threshold (S=8 == per-thread 8 consecutive cols)
//   x_new -> xn;  x_mom = x_new + mu*(x_new - x_old) -> xm
// ---------------------------------------------------------------------------
__global__ __launch_bounds__(256, 2) void fista_step_k(
    const float* __restrict__ xt, const float* __restrict__ xo,
    float* __restrict__ xn, float* __restrict__ xm, float mu)
{
    const int BM = 128, BN = 128, BK = 16, K = D_;
    __shared__ float As[BK][BM];
    __shared__ float Bs[BK][BN];

    const int c = blockIdx.z;
    const float* A  = xt + c * D_;                        // lda = CD
    const float* Bp = &g_gram[(size_t)c * D_ * D_];       // ldb = D_
    const int row0 = blockIdx.y * BM;                     // batch rows
    const int col0 = blockIdx.x * BN;                     // dict cols
    const int tid = threadIdx.x;
    const int tx = tid & 15;
    const int ty = tid >> 4;

    float acc[8][8];
#pragma unroll
    for (int i = 0; i < 8; i++)
#pragma unroll
        for (int j = 0; j < 8; j++) acc[i][j] = 0.f;

    for (int kt = 0; kt < K; kt += BK) {
#pragma unroll
        for (int l = 0; l < 2; l++) {
            int v = tid + l * 256;
            int m = v >> 2;
            int kq = (v & 3) << 2;
            float4 f = *(const float4*)(A + (size_t)(row0 + m) * CD + kt + kq);
            As[kq + 0][m] = f.x; As[kq + 1][m] = f.y;
            As[kq + 2][m] = f.z; As[kq + 3][m] = f.w;
        }
#pragma unroll
        for (int l = 0; l < 2; l++) {
            int v = tid + l * 256;
            int n = v >> 2;
            int kq = (v & 3) << 2;
            float4 f = *(const float4*)(Bp + (size_t)(col0 + n) * D_ + kt + kq);
            Bs[kq + 0][n] = f.x; Bs[kq + 1][n] = f.y;
            Bs[kq + 2][n] = f.z; Bs[kq + 3][n] = f.w;
        }
        __syncthreads();

#pragma unroll
        for (int k = 0; k < BK; k++) {
            float a[8], b[8];
            *(float4*)&a[0] = *(const float4*)&As[k][ty * 8];
            *(float4*)&a[4] = *(const float4*)&As[k][ty * 8 + 4];
            *(float4*)&b[0] = *(const float4*)&Bs[k][tx * 8];
            *(float4*)&b[4] = *(const float4*)&Bs[k][tx * 8 + 4];
#pragma unroll
            for (int i = 0; i < 8; i++)
#pragma unroll
                for (int j = 0; j < 8; j++)
                    acc[i][j] = fmaf(a[i], b[j], acc[i][j]);
        }
        __syncthreads();
    }

    // Fused epilogue: tx*8 .. tx*8+7 is exactly one sparsity group.
    const int gc = col0 + tx * 8;
#pragma unroll
    for (int i = 0; i < 8; i++) {
        int b = row0 + ty * 8 + i;
        size_t base = (size_t)b * CD + c * D_ + gc;
        float v[8];
        float ss = 0.f;
#pragma unroll
        for (int j = 0; j < 8; j++) {
            float xtv = xt[base + j];
            float yv  = g_y[base + j];
            v[j] = xtv - TAU * acc[i][j] + TAU * yv;
            ss = fmaf(v[j], v[j], ss);
        }
        float nrm = sqrtf(ss);
        float scale = fmaxf(1.f - (LAM * TAU) / nrm, 0.f);  // nrm=0 -> -inf -> 0
#pragma unroll
        for (int j = 0; j < 8; j++) {
            float z = scale * fmaxf(v[j], 0.f);
            xn[base + j] = z;
            xm[base + j] = z + mu * (z - xo[base + j]);
        }
    }
}

// ---------------------------------------------------------------------------
// Decoder NN GEMM: out[b,c,n] = sum_d z[b,c,d] * W[c,d,n]
// ---------------------------------------------------------------------------
__global__ __launch_bounds__(256, 2) void gemm_nn_dec_k(
    const float* __restrict__ Z, const float* __restrict__ W,
    float* __restrict__ Out)
{
    const int BM = 128, BN = 128, BK = 16, K = D_;
    __shared__ float As[BK][BM];
    __shared__ float Bs[BK][BN];

    const int c = blockIdx.z;
    const float* A  = Z + c * D_;                      // lda = CD
    const float* Bp = W + (size_t)c * D_ * N_;         // B[k][n], ldb = N_
    float* Cp = Out + c * N_;                          // ldc = CN
    const int row0 = blockIdx.y * BM;
    const int col0 = blockIdx.x * BN;
    const int tid = threadIdx.x;
    const int tx = tid & 15;
    const int ty = tid >> 4;

    float acc[8][8];
#pragma unroll
    for (int i = 0; i < 8; i++)
#pragma unroll
        for (int j = 0; j < 8; j++) acc[i][j] = 0.f;

    for (int kt = 0; kt < K; kt += BK) {
#pragma unroll
        for (int l = 0; l < 2; l++) {
            int v = tid + l * 256;
            int m = v >> 2;
            int kq = (v & 3) << 2;
            float4 f = *(const float4*)(A + (size_t)(row0 + m) * CD + kt + kq);
            As[kq + 0][m] = f.x; As[kq + 1][m] = f.y;
            As[kq + 2][m] = f.z; As[kq + 3][m] = f.w;
        }
#pragma unroll
        for (int l = 0; l < 2; l++) {
            int v = tid + l * 256;
            int kr = v >> 5;
            int nq = (v & 31) << 2;
            float4 f = *(const float4*)(Bp + (size_t)(kt + kr) * N_ + col0 + nq);
            *(float4*)&Bs[kr][nq] = f;
        }
        __syncthreads();

#pragma unroll
        for (int k = 0; k < BK; k++) {
            float a[8], b[8];
            *(float4*)&a[0] = *(const float4*)&As[k][ty * 8];
            *(float4*)&a[4] = *(const float4*)&As[k][ty * 8 + 4];
            *(float4*)&b[0] = *(const float4*)&Bs[k][tx * 8];
            *(float4*)&b[4] = *(const float4*)&Bs[k][tx * 8 + 4];
#pragma unroll
            for (int i = 0; i < 8; i++)
#pragma unroll
                for (int j = 0; j < 8; j++)
                    acc[i][j] = fmaf(a[i], b[j], acc[i][j]);
        }
        __syncthreads();
    }

#pragma unroll
    for (int i = 0; i < 8; i++) {
        size_t base = (size_t)(row0 + ty * 8 + i) * CN + col0 + tx * 8;
        float4 o0 = make_float4(acc[i][0], acc[i][1], acc[i][2], acc[i][3]);
        float4 o1 = make_float4(acc[i][4], acc[i][5], acc[i][6], acc[i][7]);
        *(float4*)&Cp[base] = o0;
        *(float4*)&Cp[base + 4] = o1;
    }
}

extern "C" void kernel_launch(void* const* d_in, const int* in_sizes, int n_in,
                              void* d_out, int out_size)
{
    const float* x = (const float*)d_in[0];
    const float* W = (const float*)d_in[1];
    if (in_sizes[0] != B_ * C_ * N_) {  // defensive: swap if order differs
        const float* t = x; x = W; W = t;
    }
    float* out = (float*)d_out;

    float *pg, *py, *pb0, *pb1, *pb2, *pb3;
    cudaGetSymbolAddress((void**)&pg,  g_gram);
    cudaGetSymbolAddress((void**)&py,  g_y);
    cudaGetSymbolAddress((void**)&pb0, g_b0);
    cudaGetSymbolAddress((void**)&pb1, g_b1);
    cudaGetSymbolAddress((void**)&pb2, g_b2);
    cudaGetSymbolAddress((void**)&pb3, g_b3);

    // x_old = x_tmp = 0
    int nstate = B_ * C_ * D_;
    zero2_kernel<<<(nstate + 255) / 256, 256>>>(pb0, pb1, nstate);

    // Gram[c] = W_c W_c^T  (M=N=2048, K=1024)
    gemm_nt_k<<<dim3(16, 16, 3), 256>>>(W, N_, (size_t)D_ * N_,
                                        W, N_, (size_t)D_ * N_,
                                        pg, D_, (size_t)D_ * D_, N_);
    // y[b,c,d] = sum_n x[b,c,n] W[c,d,n]  (M=512, N=2048, K=1024)
    gemm_nt_k<<<dim3(16, 4, 3), 256>>>(x, CN, (size_t)N_,
                                       W, N_, (size_t)D_ * N_,
                                       py, CD, (size_t)D_, N_);

    // 30 FISTA iterations; momentum scalars are data-independent
    float t = 1.f;
    float *xo = pb0, *xt = pb1, *xn = pb2, *xm = pb3;
    for (int it = 0; it < NLAYERS; it++) {
        float tn = (1.f + sqrtf(1.f + 4.f * t * t)) * 0.5f;
        float mu = (t - 1.f) / tn;
        fista_step_k<<<dim3(16, 4, 3), 256>>>(xt, xo, xn, xm, mu);
        float* a = xo; float* b = xt;
        xo = xn; xt = xm;   // next iteration inputs
        xn = a; xm = b;     // recycle old buffers as outputs
        t = tn;
    }

    // z = last x_new (now in xo); decoder: out = z @ W
    gemm_nn_dec_k<<<dim3(8, 4, 3), 256>>>(xo, W, out);
}

// round 10
// speedup vs baseline: 1.3858x; 1.3858x over previous
#include <cuda_runtime.h>
#include <math.h>
#include <stdint.h>

#define B_ 512
#define C_ 3
#define N_ 1024
#define D_ 2048
#define CD (C_*D_)
#define CN (C_*N_)
#define TAU 0.1f
#define LAM 0.1f
#define NLAYERS 30

// ---------------- scratch (static device globals) ----------------
__device__ float g_mh[(size_t)C_ * D_ * D_];     // hi(tf32) of M2 = TAU*G - I
__device__ float g_ml[(size_t)C_ * D_ * D_];     // lo(tf32) of M2
__device__ float g_y[(size_t)B_ * C_ * D_];      // y2 = TAU * y
__device__ float g_n0[(size_t)B_ * C_ * D_];     // z state fp32, ping
__device__ float g_n1[(size_t)B_ * C_ * D_];     // pong
__device__ float g_h0[(size_t)B_ * C_ * D_];     // momentum hi, ping
__device__ float g_h1[(size_t)B_ * C_ * D_];     // momentum hi, pong
__device__ float g_l0[(size_t)B_ * C_ * D_];     // momentum lo, ping
__device__ float g_l1[(size_t)B_ * C_ * D_];     // momentum lo, pong

// ---------------- helpers ----------------
__device__ __forceinline__ uint32_t smem_u32(const void* p) {
    uint32_t a;
    asm("{ .reg .u64 t; cvta.to.shared.u64 t, %1; cvt.u32.u64 %0, t; }" : "=r"(a) : "l"(p));
    return a;
}
__device__ __forceinline__ float tf32r(float x) {
    uint32_t u;
    asm("cvt.rna.tf32.f32 %0, %1;" : "=r"(u) : "f"(x));
    return __uint_as_float(u);
}
__device__ __forceinline__ void cp16(uint32_t dst, const void* src) {
    asm volatile("cp.async.cg.shared.global [%0], [%1], 16;" :: "r"(dst), "l"(src));
}
#define CP_COMMIT() asm volatile("cp.async.commit_group;" ::: "memory")
#define CP_WAIT1()  asm volatile("cp.async.wait_group 1;" ::: "memory")

__device__ __forceinline__ void mma_tf32(float* c, const uint32_t* a, const uint32_t* b) {
    asm volatile(
        "mma.sync.aligned.m16n8k8.row.col.f32.tf32.tf32.f32 "
        "{%0,%1,%2,%3}, {%4,%5,%6,%7}, {%8,%9}, {%0,%1,%2,%3};"
        : "+f"(c[0]), "+f"(c[1]), "+f"(c[2]), "+f"(c[3])
        : "r"(a[0]), "r"(a[1]), "r"(a[2]), "r"(a[3]), "r"(b[0]), "r"(b[1]));
}

// ---------------- fista 3xTF32 mma kernel ----------------
// CTA tile 128(batch) x 128(dict); K=2048 in BK=32 chunks, 3-stage cp.async.
// Operands pre-split into tf32 hi/lo (A: momentum state arrays; B: M2 = TAU*G - I).
// acc = xt @ M2 to ~fp32 accuracy via a_hi*b_hi + a_lo*b_hi + a_hi*b_lo.
// v = y2 - acc, then group soft-threshold + momentum, writing z and (hi,lo) state.
#define BKF 32
#define STRIDE 36
#define STG_F (128*STRIDE)
#define SMEM_FISTA (12 * STG_F * 4)   // 4 operand arrays x 3 stages = 221184 B

__global__ __launch_bounds__(256, 1) void fista_mma_k(
    const float* __restrict__ ah_in, const float* __restrict__ al_in,
    const float* __restrict__ xo_in,
    float* __restrict__ xn_out, float* __restrict__ xh_out, float* __restrict__ xl_out,
    const float* __restrict__ Mh, const float* __restrict__ Ml,
    const float* __restrict__ y2, float mu)
{
    extern __shared__ float smem[];
    float* AH = smem;                  // [3][128][STRIDE]
    float* AL = smem + 3 * STG_F;
    float* BH = smem + 6 * STG_F;
    float* BL = smem + 9 * STG_F;

    const int tid = threadIdx.x;
    const int wid = tid >> 5, lane = tid & 31;
    const int c = blockIdx.z;
    const int row0 = blockIdx.y * 128, col0 = blockIdx.x * 128;
    const int wm0 = (wid >> 2) * 64;
    const int wn0 = (wid & 3) * 32;
    const int gq = lane >> 2, tq = lane & 3;

    const float* AgH = ah_in + (size_t)row0 * CD + (size_t)c * D_;
    const float* AgL = al_in + (size_t)row0 * CD + (size_t)c * D_;
    const float* BgH = Mh + (size_t)c * D_ * D_ + (size_t)col0 * D_;
    const float* BgL = Ml + (size_t)c * D_ * D_ + (size_t)col0 * D_;

    const uint32_t ah_sm = smem_u32(AH);
    const uint32_t al_sm = smem_u32(AL);
    const uint32_t bh_sm = smem_u32(BH);
    const uint32_t bl_sm = smem_u32(BL);

    float acc[4][4][4];
#pragma unroll
    for (int mt = 0; mt < 4; mt++)
#pragma unroll
        for (int nt = 0; nt < 4; nt++)
#pragma unroll
            for (int q = 0; q < 4; q++) acc[mt][nt][q] = 0.f;

    auto load_stage = [&](int s, int ktile) {
        const size_t ko = (size_t)ktile * BKF;
#pragma unroll
        for (int l = 0; l < 4; l++) {
            int v = tid + l * 256;
            int r = v >> 3, cc = v & 7;
            uint32_t so = (uint32_t)(((s * 128 + r) * STRIDE + cc * 4) * 4);
            size_t goA = (size_t)r * CD + ko + cc * 4;
            size_t goB = (size_t)r * D_ + ko + cc * 4;
            cp16(ah_sm + so, AgH + goA);
            cp16(al_sm + so, AgL + goA);
            cp16(bh_sm + so, BgH + goB);
            cp16(bl_sm + so, BgL + goB);
        }
    };

    const int NKT = D_ / BKF;  // 64
    load_stage(0, 0); CP_COMMIT();
    load_stage(1, 1); CP_COMMIT();

    for (int kt = 0; kt < NKT; kt++) {
        CP_WAIT1();
        __syncthreads();
        if (kt + 2 < NKT) load_stage((kt + 2) % 3, kt + 2);
        CP_COMMIT();

        const int sb = (kt % 3) * STG_F;
        const float* AbH = AH + sb;
        const float* AbL = AL + sb;
        const float* BbH = BH + sb;
        const float* BbL = BL + sb;
#pragma unroll
        for (int ks = 0; ks < 4; ks++) {
            const int k0 = ks * 8;
            uint32_t ah[4][4], al[4][4], bh[4][2], bl[4][2];
#pragma unroll
            for (int mt = 0; mt < 4; mt++) {
                const int ro = (wm0 + mt * 16 + gq) * STRIDE + k0 + tq;
                ah[mt][0] = __float_as_uint(AbH[ro]);
                ah[mt][1] = __float_as_uint(AbH[ro + 8 * STRIDE]);
                ah[mt][2] = __float_as_uint(AbH[ro + 4]);
                ah[mt][3] = __float_as_uint(AbH[ro + 8 * STRIDE + 4]);
                al[mt][0] = __float_as_uint(AbL[ro]);
                al[mt][1] = __float_as_uint(AbL[ro + 8 * STRIDE]);
                al[mt][2] = __float_as_uint(AbL[ro + 4]);
                al[mt][3] = __float_as_uint(AbL[ro + 8 * STRIDE + 4]);
            }
#pragma unroll
            for (int nt = 0; nt < 4; nt++) {
                const int ro = (wn0 + nt * 8 + gq) * STRIDE + k0 + tq;
                bh[nt][0] = __float_as_uint(BbH[ro]);
                bh[nt][1] = __float_as_uint(BbH[ro + 4]);
                bl[nt][0] = __float_as_uint(BbL[ro]);
                bl[nt][1] = __float_as_uint(BbL[ro + 4]);
            }
#pragma unroll
            for (int mt = 0; mt < 4; mt++)
#pragma unroll
                for (int nt = 0; nt < 4; nt++) {
                    mma_tf32(acc[mt][nt], al[mt], bh[nt]);
                    mma_tf32(acc[mt][nt], ah[mt], bl[nt]);
                    mma_tf32(acc[mt][nt], ah[mt], bh[nt]);
                }
        }
    }
    __syncthreads();

    // ---- fused epilogue: v = y2 - acc ----
    const size_t cb = (size_t)c * D_;
#pragma unroll
    for (int mt = 0; mt < 4; mt++) {
        const int r0 = row0 + wm0 + mt * 16 + gq;
#pragma unroll
        for (int nt = 0; nt < 4; nt++) {
            const int col = col0 + wn0 + nt * 8 + 2 * tq;
            const size_t i0 = (size_t)r0 * CD + cb + col;
            const size_t i1 = i0 + (size_t)8 * CD;

            float2 y0 = *(const float2*)(y2 + i0);
            float2 y1 = *(const float2*)(y2 + i1);
            float v00 = y0.x - acc[mt][nt][0];
            float v01 = y0.y - acc[mt][nt][1];
            float v10 = y1.x - acc[mt][nt][2];
            float v11 = y1.y - acc[mt][nt][3];

            float ss0 = fmaf(v00, v00, v01 * v01);
            float ss1 = fmaf(v10, v10, v11 * v11);
            ss0 += __shfl_xor_sync(0xffffffffu, ss0, 1);
            ss0 += __shfl_xor_sync(0xffffffffu, ss0, 2);
            ss1 += __shfl_xor_sync(0xffffffffu, ss1, 1);
            ss1 += __shfl_xor_sync(0xffffffffu, ss1, 2);
            float sc0 = fmaxf(1.f - (LAM * TAU) / sqrtf(ss0), 0.f);
            float sc1 = fmaxf(1.f - (LAM * TAU) / sqrtf(ss1), 0.f);

            float2 xo0 = *(const float2*)(xo_in + i0);
            float2 xo1 = *(const float2*)(xo_in + i1);

            float z00 = sc0 * fmaxf(v00, 0.f);
            float z01 = sc0 * fmaxf(v01, 0.f);
            float z10 = sc1 * fmaxf(v10, 0.f);
            float z11 = sc1 * fmaxf(v11, 0.f);

            float m00 = fmaf(mu, z00 - xo0.x, z00);
            float m01 = fmaf(mu, z01 - xo0.y, z01);
            float m10 = fmaf(mu, z10 - xo1.x, z10);
            float m11 = fmaf(mu, z11 - xo1.y, z11);

            float h00 = tf32r(m00), h01 = tf32r(m01);
            float h10 = tf32r(m10), h11 = tf32r(m11);

            *(float2*)(xn_out + i0) = make_float2(z00, z01);
            *(float2*)(xn_out + i1) = make_float2(z10, z11);
            *(float2*)(xh_out + i0) = make_float2(h00, h01);
            *(float2*)(xh_out + i1) = make_float2(h10, h11);
            *(float2*)(xl_out + i0) = make_float2(tf32r(m00 - h00), tf32r(m01 - h01));
            *(float2*)(xl_out + i1) = make_float2(tf32r(m10 - h10), tf32r(m11 - h11));
        }
    }
}

// ---------------- elementwise helpers ----------------
__global__ void zero3_kernel(float* __restrict__ a, float* __restrict__ b,
                             float* __restrict__ d, int n) {
    int i = blockIdx.x * blockDim.x + threadIdx.x;
    if (i < n) { a[i] = 0.f; b[i] = 0.f; d[i] = 0.f; }
}

// gram (raw fp32 G) -> M2 = TAU*G - I split into (hi, lo) tf32 pairs, in place.
__global__ void make_M2_k(float* __restrict__ gh, float* __restrict__ gl) {
    size_t i = (size_t)blockIdx.x * blockDim.x + threadIdx.x;
    if (i >= (size_t)C_ * D_ * D_) return;
    int d = (int)(i % D_);
    int e = (int)((i / D_) % D_);
    float m2 = TAU * gh[i] - ((e == d) ? 1.f : 0.f);
    float hi = tf32r(m2);
    gh[i] = hi;
    gl[i] = tf32r(m2 - hi);
}

__global__ void scale_y_k(float* __restrict__ y, int n) {
    int i = blockIdx.x * blockDim.x + threadIdx.x;
    if (i < n) y[i] *= TAU;
}

// ---------------- FFMA GEMMs (Gram, y, decoder) ----------------
__global__ __launch_bounds__(256, 2) void gemm_nt_k(
    const float* __restrict__ A, int lda, size_t sA,
    const float* __restrict__ Bp, int ldb, size_t sB,
    float* __restrict__ Cp, int ldc, size_t sC, int K)
{
    const int BM = 128, BN = 128, BK = 16;
    __shared__ float As[BK][BM];
    __shared__ float Bs[BK][BN];

    A  += (size_t)blockIdx.z * sA;
    Bp += (size_t)blockIdx.z * sB;
    Cp += (size_t)blockIdx.z * sC;

    const int row0 = blockIdx.y * BM;
    const int col0 = blockIdx.x * BN;
    const int tid = threadIdx.x;
    const int tx = tid & 15;
    const int ty = tid >> 4;

    float acc[8][8];
#pragma unroll
    for (int i = 0; i < 8; i++)
#pragma unroll
        for (int j = 0; j < 8; j++) acc[i][j] = 0.f;

    for (int kt = 0; kt < K; kt += BK) {
#pragma unroll
        for (int l = 0; l < 2; l++) {
            int v = tid + l * 256;
            int m = v >> 2;
            int kq = (v & 3) << 2;
            float4 f = *(const float4*)(A + (size_t)(row0 + m) * lda + kt + kq);
            As[kq + 0][m] = f.x; As[kq + 1][m] = f.y;
            As[kq + 2][m] = f.z; As[kq + 3][m] = f.w;
        }
#pragma unroll
        for (int l = 0; l < 2; l++) {
            int v = tid + l * 256;
            int n = v >> 2;
            int kq = (v & 3) << 2;
            float4 f = *(const float4*)(Bp + (size_t)(col0 + n) * ldb + kt + kq);
            Bs[kq + 0][n] = f.x; Bs[kq + 1][n] = f.y;
            Bs[kq + 2][n] = f.z; Bs[kq + 3][n] = f.w;
        }
        __syncthreads();

#pragma unroll
        for (int k = 0; k < BK; k++) {
            float a[8], b[8];
            *(float4*)&a[0] = *(const float4*)&As[k][ty * 8];
            *(float4*)&a[4] = *(const float4*)&As[k][ty * 8 + 4];
            *(float4*)&b[0] = *(const float4*)&Bs[k][tx * 8];
            *(float4*)&b[4] = *(const float4*)&Bs[k][tx * 8 + 4];
#pragma unroll
            for (int i = 0; i < 8; i++)
#pragma unroll
                for (int j = 0; j < 8; j++)
                    acc[i][j] = fmaf(a[i], b[j], acc[i][j]);
        }
        __syncthreads();
    }

#pragma unroll
    for (int i = 0; i < 8; i++) {
        size_t base = (size_t)(row0 + ty * 8 + i) * ldc + col0 + tx * 8;
        *(float4*)&Cp[base]     = make_float4(acc[i][0], acc[i][1], acc[i][2], acc[i][3]);
        *(float4*)&Cp[base + 4] = make_float4(acc[i][4], acc[i][5], acc[i][6], acc[i][7]);
    }
}

__global__ __launch_bounds__(256, 2) void gemm_nn_dec_k(
    const float* __restrict__ Z, const float* __restrict__ W,
    float* __restrict__ Out)
{
    const int BM = 128, BN = 128, BK = 16, K = D_;
    __shared__ float As[BK][BM];
    __shared__ float Bs[BK][BN];

    const int c = blockIdx.z;
    const float* A  = Z + c * D_;
    const float* Bp = W + (size_t)c * D_ * N_;
    float* Cp = Out + c * N_;
    const int row0 = blockIdx.y * BM;
    const int col0 = blockIdx.x * BN;
    const int tid = threadIdx.x;
    const int tx = tid & 15;
    const int ty = tid >> 4;

    float acc[8][8];
#pragma unroll
    for (int i = 0; i < 8; i++)
#pragma unroll
        for (int j = 0; j < 8; j++) acc[i][j] = 0.f;

    for (int kt = 0; kt < K; kt += BK) {
#pragma unroll
        for (int l = 0; l < 2; l++) {
            int v = tid + l * 256;
            int m = v >> 2;
            int kq = (v & 3) << 2;
            float4 f = *(const float4*)(A + (size_t)(row0 + m) * CD + kt + kq);
            As[kq + 0][m] = f.x; As[kq + 1][m] = f.y;
            As[kq + 2][m] = f.z; As[kq + 3][m] = f.w;
        }
#pragma unroll
        for (int l = 0; l < 2; l++) {
            int v = tid + l * 256;
            int kr = v >> 5;
            int nq = (v & 31) << 2;
            float4 f = *(const float4*)(Bp + (size_t)(kt + kr) * N_ + col0 + nq);
            *(float4*)&Bs[kr][nq] = f;
        }
        __syncthreads();

#pragma unroll
        for (int k = 0; k < BK; k++) {
            float a[8], b[8];
            *(float4*)&a[0] = *(const float4*)&As[k][ty * 8];
            *(float4*)&a[4] = *(const float4*)&As[k][ty * 8 + 4];
            *(float4*)&b[0] = *(const float4*)&Bs[k][tx * 8];
            *(float4*)&b[4] = *(const float4*)&Bs[k][tx * 8 + 4];
#pragma unroll
            for (int i = 0; i < 8; i++)
#pragma unroll
                for (int j = 0; j < 8; j++)
                    acc[i][j] = fmaf(a[i], b[j], acc[i][j]);
        }
        __syncthreads();
    }

#pragma unroll
    for (int i = 0; i < 8; i++) {
        size_t base = (size_t)(row0 + ty * 8 + i) * CN + col0 + tx * 8;
        *(float4*)&Cp[base]     = make_float4(acc[i][0], acc[i][1], acc[i][2], acc[i][3]);
        *(float4*)&Cp[base + 4] = make_float4(acc[i][4], acc[i][5], acc[i][6], acc[i][7]);
    }
}

extern "C" void kernel_launch(void* const* d_in, const int* in_sizes, int n_in,
                              void* d_out, int out_size)
{
    const float* x = (const float*)d_in[0];
    const float* W = (const float*)d_in[1];
    if (in_sizes[0] != B_ * C_ * N_) { const float* t = x; x = W; W = t; }
    float* out = (float*)d_out;

    float *pmh, *pml, *py, *pn0, *pn1, *ph0, *ph1, *pl0, *pl1;
    cudaGetSymbolAddress((void**)&pmh, g_mh);
    cudaGetSymbolAddress((void**)&pml, g_ml);
    cudaGetSymbolAddress((void**)&py,  g_y);
    cudaGetSymbolAddress((void**)&pn0, g_n0);
    cudaGetSymbolAddress((void**)&pn1, g_n1);
    cudaGetSymbolAddress((void**)&ph0, g_h0);
    cudaGetSymbolAddress((void**)&ph1, g_h1);
    cudaGetSymbolAddress((void**)&pl0, g_l0);
    cudaGetSymbolAddress((void**)&pl1, g_l1);

    static int smem_set = 0;
    if (!smem_set) {
        cudaFuncSetAttribute(fista_mma_k, cudaFuncAttributeMaxDynamicSharedMemorySize,
                             SMEM_FISTA);
        smem_set = 1;
    }

    const int nstate = B_ * C_ * D_;
    // z_old = 0, momentum hi/lo = 0
    zero3_kernel<<<(nstate + 255) / 256, 256>>>(pn0, ph0, pl0, nstate);

    // Gram[c] = W_c W_c^T (exact fp32) -> into g_mh temp
    gemm_nt_k<<<dim3(16, 16, 3), 256>>>(W, N_, (size_t)D_ * N_,
                                        W, N_, (size_t)D_ * N_,
                                        pmh, D_, (size_t)D_ * D_, N_);
    // y[b,c,d] = sum_n x W (exact fp32)
    gemm_nt_k<<<dim3(16, 4, 3), 256>>>(x, CN, (size_t)N_,
                                       W, N_, (size_t)D_ * N_,
                                       py, CD, (size_t)D_, N_);
    // M2 = TAU*G - I split into tf32 (hi, lo); y2 = TAU*y
    {
        size_t ng = (size_t)C_ * D_ * D_;
        make_M2_k<<<(unsigned)((ng + 255) / 256), 256>>>(pmh, pml);
        scale_y_k<<<(nstate + 255) / 256, 256>>>(py, nstate);
    }

    // 30 FISTA iterations: 3xTF32 split-precision tensor-core GEMM
    float t = 1.f;
    float *hi_i = ph0, *lo_i = pl0, *hi_o = ph1, *lo_o = pl1;
    float *no = pn0, *nn = pn1;
    for (int it = 0; it < NLAYERS; it++) {
        float tnv = (1.f + sqrtf(1.f + 4.f * t * t)) * 0.5f;
        float mu = (t - 1.f) / tnv;
        fista_mma_k<<<dim3(D_ / 128, B_ / 128, C_), 256, SMEM_FISTA>>>(
            hi_i, lo_i, no, nn, hi_o, lo_o, pmh, pml, py, mu);
        float* tmp;
        tmp = hi_i; hi_i = hi_o; hi_o = tmp;
        tmp = lo_i; lo_i = lo_o; lo_o = tmp;
        tmp = no; no = nn; nn = tmp;
        t = tnv;
    }

    // decoder: out = z @ W (exact fp32); final z is in `no` after last swap
    gemm_nn_dec_k<<<dim3(8, 4, 3), 256>>>(no, W, out);
}

// round 11
// speedup vs baseline: 1.7080x; 1.2325x over previous
#include <cuda_runtime.h>
#include <math.h>
#include <stdint.h>

#define B_ 512
#define C_ 3
#define N_ 1024
#define D_ 2048
#define CD (C_*D_)
#define CN (C_*N_)
#define TAU 0.1f
#define LAM 0.1f
#define NLAYERS 30

// ---------------- scratch (static device globals) ----------------
__device__ float g_mh[(size_t)C_ * D_ * D_];     // hi(tf32) of M2 = TAU*G - I
__device__ float g_ml[(size_t)C_ * D_ * D_];     // lo(tf32) of M2
__device__ float g_y[(size_t)B_ * C_ * D_];      // y2 = TAU * y
__device__ float g_n0[(size_t)B_ * C_ * D_];     // z state fp32, ping
__device__ float g_n1[(size_t)B_ * C_ * D_];     // pong
__device__ float g_h0[(size_t)B_ * C_ * D_];     // momentum hi, ping
__device__ float g_h1[(size_t)B_ * C_ * D_];     // momentum hi, pong
__device__ float g_l0[(size_t)B_ * C_ * D_];     // momentum lo, ping
__device__ float g_l1[(size_t)B_ * C_ * D_];     // momentum lo, pong

// ---------------- helpers ----------------
__device__ __forceinline__ uint32_t smem_u32(const void* p) {
    uint32_t a;
    asm("{ .reg .u64 t; cvta.to.shared.u64 t, %1; cvt.u32.u64 %0, t; }" : "=r"(a) : "l"(p));
    return a;
}
__device__ __forceinline__ float tf32r(float x) {
    uint32_t u;
    asm("cvt.rna.tf32.f32 %0, %1;" : "=r"(u) : "f"(x));
    return __uint_as_float(u);
}
__device__ __forceinline__ void cp16(uint32_t dst, const void* src) {
    asm volatile("cp.async.cg.shared.global [%0], [%1], 16;" :: "r"(dst), "l"(src));
}
#define CP_COMMIT() asm volatile("cp.async.commit_group;" ::: "memory")
#define CP_WAIT1()  asm volatile("cp.async.wait_group 1;" ::: "memory")
#define CP_WAIT0()  asm volatile("cp.async.wait_group 0;" ::: "memory")

__device__ __forceinline__ void mma_tf32(float* c, const uint32_t* a, const uint32_t* b) {
    asm volatile(
        "mma.sync.aligned.m16n8k8.row.col.f32.tf32.tf32.f32 "
        "{%0,%1,%2,%3}, {%4,%5,%6,%7}, {%8,%9}, {%0,%1,%2,%3};"
        : "+f"(c[0]), "+f"(c[1]), "+f"(c[2]), "+f"(c[3])
        : "r"(a[0]), "r"(a[1]), "r"(a[2]), "r"(a[3]), "r"(b[0]), "r"(b[1]));
}

// ---------------- fista 3xTF32 mma kernel ----------------
// CTA tile 64(batch) x 128(dict); K=2048 in BK=32 chunks, 2-stage cp.async.
// 110.6KB smem -> 2 CTAs/SM (16 warps/SM). Warp tile 32x32 (8 warps: 2m x 4n).
// acc = xt @ M2 (M2 = TAU*G - I, split tf32 hi/lo both sides; 3 MMAs/product).
// v = y2 - acc, then group soft-threshold + momentum, writing z and (hi,lo) state.
#define TMF 64
#define TNF 128
#define BKF 32
#define STRIDE 36
#define A_ST (TMF*STRIDE)            // 2304 floats per stage
#define B_ST (TNF*STRIDE)            // 4608 floats per stage
#define SMEM_FISTA ((4*A_ST + 4*B_ST) * 4)   // 110592 B

__global__ __launch_bounds__(256, 2) void fista_mma_k(
    const float* __restrict__ ah_in, const float* __restrict__ al_in,
    const float* __restrict__ xo_in,
    float* __restrict__ xn_out, float* __restrict__ xh_out, float* __restrict__ xl_out,
    const float* __restrict__ Mh, const float* __restrict__ Ml,
    const float* __restrict__ y2, float mu)
{
    extern __shared__ float smem[];
    float* AH = smem;                    // [2][TMF][STRIDE]
    float* AL = smem + 2 * A_ST;
    float* BH = smem + 4 * A_ST;         // [2][TNF][STRIDE]
    float* BL = smem + 4 * A_ST + 2 * B_ST;

    const int tid = threadIdx.x;
    const int wid = tid >> 5, lane = tid & 31;
    const int c = blockIdx.z;
    const int row0 = blockIdx.y * TMF, col0 = blockIdx.x * TNF;
    const int wm0 = (wid >> 2) * 32;
    const int wn0 = (wid & 3) * 32;
    const int gq = lane >> 2, tq = lane & 3;

    const float* AgH = ah_in + (size_t)row0 * CD + (size_t)c * D_;
    const float* AgL = al_in + (size_t)row0 * CD + (size_t)c * D_;
    const float* BgH = Mh + (size_t)c * D_ * D_ + (size_t)col0 * D_;
    const float* BgL = Ml + (size_t)c * D_ * D_ + (size_t)col0 * D_;

    const uint32_t ah_sm = smem_u32(AH);
    const uint32_t al_sm = smem_u32(AL);
    const uint32_t bh_sm = smem_u32(BH);
    const uint32_t bl_sm = smem_u32(BL);

    float acc[2][4][4];
#pragma unroll
    for (int mt = 0; mt < 2; mt++)
#pragma unroll
        for (int nt = 0; nt < 4; nt++)
#pragma unroll
            for (int q = 0; q < 4; q++) acc[mt][nt][q] = 0.f;

    auto load_stage = [&](int s, int ktile) {
        const size_t ko = (size_t)ktile * BKF;
#pragma unroll
        for (int l = 0; l < 2; l++) {
            int v = tid + l * 256;               // 512 chunks for A
            int r = v >> 3, cc = v & 7;
            uint32_t so = (uint32_t)(((s * TMF + r) * STRIDE + cc * 4) * 4);
            size_t go = (size_t)r * CD + ko + cc * 4;
            cp16(ah_sm + so, AgH + go);
            cp16(al_sm + so, AgL + go);
        }
#pragma unroll
        for (int l = 0; l < 4; l++) {
            int v = tid + l * 256;               // 1024 chunks for B
            int r = v >> 3, cc = v & 7;
            uint32_t so = (uint32_t)(((s * TNF + r) * STRIDE + cc * 4) * 4);
            size_t go = (size_t)r * D_ + ko + cc * 4;
            cp16(bh_sm + so, BgH + go);
            cp16(bl_sm + so, BgL + go);
        }
    };

    const int NKT = D_ / BKF;  // 64
    load_stage(0, 0); CP_COMMIT();

    for (int kt = 0; kt < NKT; kt++) {
        __syncthreads();   // all warps done reading the stage we're about to refill
        if (kt + 1 < NKT) {
            load_stage((kt + 1) & 1, kt + 1);
            CP_COMMIT();
            CP_WAIT1();
        } else {
            CP_WAIT0();
        }
        __syncthreads();

        const int sa = (kt & 1) * A_ST;
        const int sb = (kt & 1) * B_ST;
        const float* AbH = AH + sa;
        const float* AbL = AL + sa;
        const float* BbH = BH + sb;
        const float* BbL = BL + sb;
#pragma unroll
        for (int ks = 0; ks < 4; ks++) {
            const int k0 = ks * 8;
            uint32_t ah[2][4], al[2][4], bh[4][2], bl[4][2];
#pragma unroll
            for (int mt = 0; mt < 2; mt++) {
                const int ro = (wm0 + mt * 16 + gq) * STRIDE + k0 + tq;
                ah[mt][0] = __float_as_uint(AbH[ro]);
                ah[mt][1] = __float_as_uint(AbH[ro + 8 * STRIDE]);
                ah[mt][2] = __float_as_uint(AbH[ro + 4]);
                ah[mt][3] = __float_as_uint(AbH[ro + 8 * STRIDE + 4]);
                al[mt][0] = __float_as_uint(AbL[ro]);
                al[mt][1] = __float_as_uint(AbL[ro + 8 * STRIDE]);
                al[mt][2] = __float_as_uint(AbL[ro + 4]);
                al[mt][3] = __float_as_uint(AbL[ro + 8 * STRIDE + 4]);
            }
#pragma unroll
            for (int nt = 0; nt < 4; nt++) {
                const int ro = (wn0 + nt * 8 + gq) * STRIDE + k0 + tq;
                bh[nt][0] = __float_as_uint(BbH[ro]);
                bh[nt][1] = __float_as_uint(BbH[ro + 4]);
                bl[nt][0] = __float_as_uint(BbL[ro]);
                bl[nt][1] = __float_as_uint(BbL[ro + 4]);
            }
#pragma unroll
            for (int mt = 0; mt < 2; mt++)
#pragma unroll
                for (int nt = 0; nt < 4; nt++) {
                    mma_tf32(acc[mt][nt], al[mt], bh[nt]);
                    mma_tf32(acc[mt][nt], ah[mt], bl[nt]);
                    mma_tf32(acc[mt][nt], ah[mt], bh[nt]);
                }
        }
    }

    // ---- fused epilogue: v = y2 - acc ----
    const size_t cb = (size_t)c * D_;
#pragma unroll
    for (int mt = 0; mt < 2; mt++) {
        const int r0 = row0 + wm0 + mt * 16 + gq;
#pragma unroll
        for (int nt = 0; nt < 4; nt++) {
            const int col = col0 + wn0 + nt * 8 + 2 * tq;
            const size_t i0 = (size_t)r0 * CD + cb + col;
            const size_t i1 = i0 + (size_t)8 * CD;

            float2 y0 = *(const float2*)(y2 + i0);
            float2 y1 = *(const float2*)(y2 + i1);
            float v00 = y0.x - acc[mt][nt][0];
            float v01 = y0.y - acc[mt][nt][1];
            float v10 = y1.x - acc[mt][nt][2];
            float v11 = y1.y - acc[mt][nt][3];

            float ss0 = fmaf(v00, v00, v01 * v01);
            float ss1 = fmaf(v10, v10, v11 * v11);
            ss0 += __shfl_xor_sync(0xffffffffu, ss0, 1);
            ss0 += __shfl_xor_sync(0xffffffffu, ss0, 2);
            ss1 += __shfl_xor_sync(0xffffffffu, ss1, 1);
            ss1 += __shfl_xor_sync(0xffffffffu, ss1, 2);
            float sc0 = fmaxf(1.f - (LAM * TAU) / sqrtf(ss0), 0.f);
            float sc1 = fmaxf(1.f - (LAM * TAU) / sqrtf(ss1), 0.f);

            float2 xo0 = *(const float2*)(xo_in + i0);
            float2 xo1 = *(const float2*)(xo_in + i1);

            float z00 = sc0 * fmaxf(v00, 0.f);
            float z01 = sc0 * fmaxf(v01, 0.f);
            float z10 = sc1 * fmaxf(v10, 0.f);
            float z11 = sc1 * fmaxf(v11, 0.f);

            float m00 = fmaf(mu, z00 - xo0.x, z00);
            float m01 = fmaf(mu, z01 - xo0.y, z01);
            float m10 = fmaf(mu, z10 - xo1.x, z10);
            float m11 = fmaf(mu, z11 - xo1.y, z11);

            float h00 = tf32r(m00), h01 = tf32r(m01);
            float h10 = tf32r(m10), h11 = tf32r(m11);

            *(float2*)(xn_out + i0) = make_float2(z00, z01);
            *(float2*)(xn_out + i1) = make_float2(z10, z11);
            *(float2*)(xh_out + i0) = make_float2(h00, h01);
            *(float2*)(xh_out + i1) = make_float2(h10, h11);
            *(float2*)(xl_out + i0) = make_float2(tf32r(m00 - h00), tf32r(m01 - h01));
            *(float2*)(xl_out + i1) = make_float2(tf32r(m10 - h10), tf32r(m11 - h11));
        }
    }
}

// ---------------- elementwise helpers ----------------
__global__ void zero3_kernel(float* __restrict__ a, float* __restrict__ b,
                             float* __restrict__ d, int n) {
    int i = blockIdx.x * blockDim.x + threadIdx.x;
    if (i < n) { a[i] = 0.f; b[i] = 0.f; d[i] = 0.f; }
}

// gram (raw fp32 G) -> M2 = TAU*G - I split into (hi, lo) tf32 pairs, in place.
__global__ void make_M2_k(float* __restrict__ gh, float* __restrict__ gl) {
    size_t i = (size_t)blockIdx.x * blockDim.x + threadIdx.x;
    if (i >= (size_t)C_ * D_ * D_) return;
    int d = (int)(i % D_);
    int e = (int)((i / D_) % D_);
    float m2 = TAU * gh[i] - ((e == d) ? 1.f : 0.f);
    float hi = tf32r(m2);
    gh[i] = hi;
    gl[i] = tf32r(m2 - hi);
}

__global__ void scale_y_k(float* __restrict__ y, int n) {
    int i = blockIdx.x * blockDim.x + threadIdx.x;
    if (i < n) y[i] *= TAU;
}

// ---------------- FFMA GEMMs (Gram, y, decoder) ----------------
__global__ __launch_bounds__(256, 2) void gemm_nt_k(
    const float* __restrict__ A, int lda, size_t sA,
    const float* __restrict__ Bp, int ldb, size_t sB,
    float* __restrict__ Cp, int ldc, size_t sC, int K)
{
    const int BM = 128, BN = 128, BK = 16;
    __shared__ float As[BK][BM];
    __shared__ float Bs[BK][BN];

    A  += (size_t)blockIdx.z * sA;
    Bp += (size_t)blockIdx.z * sB;
    Cp += (size_t)blockIdx.z * sC;

    const int row0 = blockIdx.y * BM;
    const int col0 = blockIdx.x * BN;
    const int tid = threadIdx.x;
    const int tx = tid & 15;
    const int ty = tid >> 4;

    float acc[8][8];
#pragma unroll
    for (int i = 0; i < 8; i++)
#pragma unroll
        for (int j = 0; j < 8; j++) acc[i][j] = 0.f;

    for (int kt = 0; kt < K; kt += BK) {
#pragma unroll
        for (int l = 0; l < 2; l++) {
            int v = tid + l * 256;
            int m = v >> 2;
            int kq = (v & 3) << 2;
            float4 f = *(const float4*)(A + (size_t)(row0 + m) * lda + kt + kq);
            As[kq + 0][m] = f.x; As[kq + 1][m] = f.y;
            As[kq + 2][m] = f.z; As[kq + 3][m] = f.w;
        }
#pragma unroll
        for (int l = 0; l < 2; l++) {
            int v = tid + l * 256;
            int n = v >> 2;
            int kq = (v & 3) << 2;
            float4 f = *(const float4*)(Bp + (size_t)(col0 + n) * ldb + kt + kq);
            Bs[kq + 0][n] = f.x; Bs[kq + 1][n] = f.y;
            Bs[kq + 2][n] = f.z; Bs[kq + 3][n] = f.w;
        }
        __syncthreads();

#pragma unroll
        for (int k = 0; k < BK; k++) {
            float a[8], b[8];
            *(float4*)&a[0] = *(const float4*)&As[k][ty * 8];
            *(float4*)&a[4] = *(const float4*)&As[k][ty * 8 + 4];
            *(float4*)&b[0] = *(const float4*)&Bs[k][tx * 8];
            *(float4*)&b[4] = *(const float4*)&Bs[k][tx * 8 + 4];
#pragma unroll
            for (int i = 0; i < 8; i++)
#pragma unroll
                for (int j = 0; j < 8; j++)
                    acc[i][j] = fmaf(a[i], b[j], acc[i][j]);
        }
        __syncthreads();
    }

#pragma unroll
    for (int i = 0; i < 8; i++) {
        size_t base = (size_t)(row0 + ty * 8 + i) * ldc + col0 + tx * 8;
        *(float4*)&Cp[base]     = make_float4(acc[i][0], acc[i][1], acc[i][2], acc[i][3]);
        *(float4*)&Cp[base + 4] = make_float4(acc[i][4], acc[i][5], acc[i][6], acc[i][7]);
    }
}

__global__ __launch_bounds__(256, 2) void gemm_nn_dec_k(
    const float* __restrict__ Z, const float* __restrict__ W,
    float* __restrict__ Out)
{
    const int BM = 128, BN = 128, BK = 16, K = D_;
    __shared__ float As[BK][BM];
    __shared__ float Bs[BK][BN];

    const int c = blockIdx.z;
    const float* A  = Z + c * D_;
    const float* Bp = W + (size_t)c * D_ * N_;
    float* Cp = Out + c * N_;
    const int row0 = blockIdx.y * BM;
    const int col0 = blockIdx.x * BN;
    const int tid = threadIdx.x;
    const int tx = tid & 15;
    const int ty = tid >> 4;

    float acc[8][8];
#pragma unroll
    for (int i = 0; i < 8; i++)
#pragma unroll
        for (int j = 0; j < 8; j++) acc[i][j] = 0.f;

    for (int kt = 0; kt < K; kt += BK) {
#pragma unroll
        for (int l = 0; l < 2; l++) {
            int v = tid + l * 256;
            int m = v >> 2;
            int kq = (v & 3) << 2;
            float4 f = *(const float4*)(A + (size_t)(row0 + m) * CD + kt + kq);
            As[kq + 0][m] = f.x; As[kq + 1][m] = f.y;
            As[kq + 2][m] = f.z; As[kq + 3][m] = f.w;
        }
#pragma unroll
        for (int l = 0; l < 2; l++) {
            int v = tid + l * 256;
            int kr = v >> 5;
            int nq = (v & 31) << 2;
            float4 f = *(const float4*)(Bp + (size_t)(kt + kr) * N_ + col0 + nq);
            *(float4*)&Bs[kr][nq] = f;
        }
        __syncthreads();

#pragma unroll
        for (int k = 0; k < BK; k++) {
            float a[8], b[8];
            *(float4*)&a[0] = *(const float4*)&As[k][ty * 8];
            *(float4*)&a[4] = *(const float4*)&As[k][ty * 8 + 4];
            *(float4*)&b[0] = *(const float4*)&Bs[k][tx * 8];
            *(float4*)&b[4] = *(const float4*)&Bs[k][tx * 8 + 4];
#pragma unroll
            for (int i = 0; i < 8; i++)
#pragma unroll
                for (int j = 0; j < 8; j++)
                    acc[i][j] = fmaf(a[i], b[j], acc[i][j]);
        }
        __syncthreads();
    }

#pragma unroll
    for (int i = 0; i < 8; i++) {
        size_t base = (size_t)(row0 + ty * 8 + i) * CN + col0 + tx * 8;
        *(float4*)&Cp[base]     = make_float4(acc[i][0], acc[i][1], acc[i][2], acc[i][3]);
        *(float4*)&Cp[base + 4] = make_float4(acc[i][4], acc[i][5], acc[i][6], acc[i][7]);
    }
}

extern "C" void kernel_launch(void* const* d_in, const int* in_sizes, int n_in,
                              void* d_out, int out_size)
{
    const float* x = (const float*)d_in[0];
    const float* W = (const float*)d_in[1];
    if (in_sizes[0] != B_ * C_ * N_) { const float* t = x; x = W; W = t; }
    float* out = (float*)d_out;

    float *pmh, *pml, *py, *pn0, *pn1, *ph0, *ph1, *pl0, *pl1;
    cudaGetSymbolAddress((void**)&pmh, g_mh);
    cudaGetSymbolAddress((void**)&pml, g_ml);
    cudaGetSymbolAddress((void**)&py,  g_y);
    cudaGetSymbolAddress((void**)&pn0, g_n0);
    cudaGetSymbolAddress((void**)&pn1, g_n1);
    cudaGetSymbolAddress((void**)&ph0, g_h0);
    cudaGetSymbolAddress((void**)&ph1, g_h1);
    cudaGetSymbolAddress((void**)&pl0, g_l0);
    cudaGetSymbolAddress((void**)&pl1, g_l1);

    static int smem_set = 0;
    if (!smem_set) {
        cudaFuncSetAttribute(fista_mma_k, cudaFuncAttributeMaxDynamicSharedMemorySize,
                             SMEM_FISTA);
        smem_set = 1;
    }

    const int nstate = B_ * C_ * D_;
    // z_old = 0, momentum hi/lo = 0
    zero3_kernel<<<(nstate + 255) / 256, 256>>>(pn0, ph0, pl0, nstate);

    // Gram[c] = W_c W_c^T (exact fp32) -> into g_mh temp
    gemm_nt_k<<<dim3(16, 16, 3), 256>>>(W, N_, (size_t)D_ * N_,
                                        W, N_, (size_t)D_ * N_,
                                        pmh, D_, (size_t)D_ * D_, N_);
    // y[b,c,d] = sum_n x W (exact fp32)
    gemm_nt_k<<<dim3(16, 4, 3), 256>>>(x, CN, (size_t)N_,
                                       W, N_, (size_t)D_ * N_,
                                       py, CD, (size_t)D_, N_);
    // M2 = TAU*G - I split into tf32 (hi, lo); y2 = TAU*y
    {
        size_t ng = (size_t)C_ * D_ * D_;
        make_M2_k<<<(unsigned)((ng + 255) / 256), 256>>>(pmh, pml);
        scale_y_k<<<(nstate + 255) / 256, 256>>>(py, nstate);
    }

    // 30 FISTA iterations: 3xTF32 split-precision tensor-core GEMM
    float t = 1.f;
    float *hi_i = ph0, *lo_i = pl0, *hi_o = ph1, *lo_o = pl1;
    float *no = pn0, *nn = pn1;
    for (int it = 0; it < NLAYERS; it++) {
        float tnv = (1.f + sqrtf(1.f + 4.f * t * t)) * 0.5f;
        float mu = (t - 1.f) / tnv;
        fista_mma_k<<<dim3(D_ / TNF, B_ / TMF, C_), 256, SMEM_FISTA>>>(
            hi_i, lo_i, no, nn, hi_o, lo_o, pmh, pml, py, mu);
        float* tmp;
        tmp = hi_i; hi_i = hi_o; hi_o = tmp;
        tmp = lo_i; lo_i = lo_o; lo_o = tmp;
        tmp = no; no = nn; nn = tmp;
        t = tnv;
    }

    // decoder: out = z @ W (exact fp32); final z is in `no` after last swap
    gemm_nn_dec_k<<<dim3(8, 4, 3), 256>>>(no, W, out);
}